// round 4
// baseline (speedup 1.0000x reference)
#include <cuda_runtime.h>
#include <cuda_bf16.h>
#include <math.h>

// Problem constants
#define BATCH 4
#define NN 4096
#define DD 256
#define PP 64
#define ALPHA 0.2f
#define KCAP 255

// Scratch (no cudaMalloc allowed)
__device__ float g_v[BATCH][DD];            // Wk @ q / sqrt(64)
__device__ float g_hp[BATCH][8][128];       // theta MLP partials (pre-bias)
__device__ float g_theta[BATCH];
__device__ unsigned long long g_kth[BATCH]; // kth key (0 => no trim)

// ---------------------------------------------------------------------------
// Kernel A: setup. grid = BATCH + BATCH*8, block=256.
//  blocks [0,BATCH): per-batch seed -> q -> v  (reads Wq+Wk, 128 KB)
//  blocks [BATCH,..): theta-MLP partial: 64-input slice -> g_hp[b][chunk][128]
// ---------------------------------------------------------------------------
__global__ void __launch_bounds__(256) setup_kernel(
        const float* __restrict__ x,
        const float* __restrict__ cmask,
        const float* __restrict__ seed_ctx,
        const float* __restrict__ local_stats,
        const float* __restrict__ Wq,
        const float* __restrict__ Wk,
        const float* __restrict__ w1)
{
    const int t = threadIdx.x;

    if (blockIdx.x >= BATCH) {
        // ---- theta MLP partial ----
        __shared__ float s_hp[2][128];
        const int m     = blockIdx.x - BATCH;
        const int b     = m >> 3;
        const int chunk = m & 7;            // 64 inputs
        const int h     = t & 127;
        const int half  = t >> 7;           // 0/1, 32 inputs each
        float a = 0.f;
        #pragma unroll 8
        for (int ii = 0; ii < 32; ii++) {
            int g = chunk * 64 + half * 32 + ii;
            float inv = (g < 384) ? seed_ctx[(size_t)b * 384 + g]
                                  : local_stats[(size_t)b * 128 + (g - 384)];
            a += inv * w1[g * 128 + h];     // coalesced across h
        }
        s_hp[half][h] = a;
        __syncthreads();
        if (t < 128) g_hp[b][chunk][t] = s_hp[0][t] + s_hp[1][t];
        return;
    }

    // ---- seed -> q -> v ----
    __shared__ int   s_seed;
    __shared__ __align__(16) float s_x[DD];
    __shared__ __align__(16) float s_q[PP];
    __shared__ __align__(16) float s_qpart[4][PP];

    const int b    = blockIdx.x;
    const int lane = t & 31;

    if (t == 0) s_seed = NN;
    __syncthreads();

    {   // first index with cmask > 0.5
        int lm = NN;
        #pragma unroll
        for (int j = 15; j >= 0; j--) {
            int i = j * 256 + t;
            if (cmask[(size_t)b * NN + i] > 0.5f) lm = i;
        }
        #pragma unroll
        for (int o = 16; o > 0; o >>= 1)
            lm = min(lm, __shfl_xor_sync(0xffffffffu, lm, o));
        if (lane == 0 && lm < NN) atomicMin(&s_seed, lm);
    }
    __syncthreads();
    const int seed = (s_seed < NN) ? s_seed : 0;

    s_x[t] = x[((size_t)b * NN + seed) * DD + t];
    __syncthreads();

    {   // q[p] = sum_d x_seed[d] * Wq[d,p]
        const int p = t & 63;
        const int c = t >> 6;               // 4 chunks of 64 d's
        float acc = 0.f;
        #pragma unroll 8
        for (int dd = 0; dd < 64; dd++) {
            int d = c * 64 + dd;
            acc += s_x[d] * Wq[d * PP + p];
        }
        s_qpart[c][p] = acc;
    }
    __syncthreads();
    if (t < PP) s_q[t] = s_qpart[0][t] + s_qpart[1][t] + s_qpart[2][t] + s_qpart[3][t];
    __syncthreads();

    {   // v[d] = (Wk[d,:] . q) / 8 ; 4 lanes per row, float4
        const int j = t & 3;
        const float4* q4 = (const float4*)(s_q + j * 16);
        float4 qv0 = q4[0], qv1 = q4[1], qv2 = q4[2], qv3 = q4[3];
        #pragma unroll
        for (int pass = 0; pass < 4; pass++) {
            const int d = pass * 64 + (t >> 2);
            const float4* wk4 = (const float4*)(Wk + d * PP + j * 16);
            float4 w0 = wk4[0], w1v = wk4[1], w2v = wk4[2], w3v = wk4[3];
            float a = w0.x*qv0.x + w0.y*qv0.y + w0.z*qv0.z + w0.w*qv0.w
                    + w1v.x*qv1.x + w1v.y*qv1.y + w1v.z*qv1.z + w1v.w*qv1.w
                    + w2v.x*qv2.x + w2v.y*qv2.y + w2v.z*qv2.z + w2v.w*qv2.w
                    + w3v.x*qv3.x + w3v.y*qv3.y + w3v.z*qv3.z + w3v.w*qv3.w;
            a += __shfl_xor_sync(0xffffffffu, a, 1);
            a += __shfl_xor_sync(0xffffffffu, a, 2);
            if (j == 0) g_v[b][d] = a * 0.125f;
        }
    }
}

// ---------------------------------------------------------------------------
// Kernel B: streaming kernel. One warp per adjacency row, 16 rows/block.
// grid = BATCH * 256, block = 512. Writes RAW scores (theta applied later).
// ---------------------------------------------------------------------------
__global__ void __launch_bounds__(512) main_kernel(
        const float* __restrict__ x,
        const float* __restrict__ adj,
        const float* __restrict__ cmask,
        float* __restrict__ out_score)
{
    __shared__ __align__(16) float s_cm[NN];
    __shared__ __align__(16) float s_v[DD];

    const int b   = blockIdx.x >> 8;
    const int blk = blockIdx.x & 255;
    const int tid = threadIdx.x;

    {
        const float4* cm4 = (const float4*)(cmask + (size_t)b * NN);
        float4* s4 = (float4*)s_cm;
        #pragma unroll
        for (int i = tid; i < NN / 4; i += 512) s4[i] = cm4[i];
        if (tid < DD) s_v[tid] = g_v[b][tid];
    }
    __syncthreads();

    const int w    = tid >> 5;
    const int lane = tid & 31;
    const int n    = (blk << 4) + w;

    const float4* a4 = (const float4*)(adj + ((size_t)b * NN + n) * NN);
    const float4* c4 = (const float4*)s_cm;

    float e2c = 0.f, deg = 0.f;
    #pragma unroll 8
    for (int i = lane; i < NN / 4; i += 32) {
        float4 a = a4[i];
        float4 c = c4[i];
        deg += (a.x + a.y) + (a.z + a.w);
        e2c += a.x * c.x + a.y * c.y + a.z * c.z + a.w * c.w;
    }

    float sc = 0.f;
    const float4* x4 = (const float4*)(x + ((size_t)b * NN + n) * DD);
    const float4* v4 = (const float4*)s_v;
    #pragma unroll
    for (int i = lane; i < DD / 4; i += 32) {
        float4 xv = x4[i];
        float4 vv = v4[i];
        sc += xv.x * vv.x + xv.y * vv.y + xv.z * vv.z + xv.w * vv.w;
    }

    #pragma unroll
    for (int o = 16; o > 0; o >>= 1) {
        e2c += __shfl_xor_sync(0xffffffffu, e2c, o);
        deg += __shfl_xor_sync(0xffffffffu, deg, o);
        sc  += __shfl_xor_sync(0xffffffffu, sc,  o);
    }

    if (lane == 0) {
        deg = fmaxf(deg, 1.0f);
        out_score[(size_t)b * NN + n] = sc + ALPHA * (e2c / deg);
    }
}

// ---------------------------------------------------------------------------
// Kernel C: per-batch select. grid=BATCH, block=1024.
// Reduces theta-MLP partials, builds p, counts, radix-selects kth key (exact
// jax top-k tie semantics), computes trimmed sums deterministically, writes
// tail stats and g_theta / g_kth for the write kernel.
// ---------------------------------------------------------------------------
__global__ void __launch_bounds__(1024) select_kernel(
        const float* __restrict__ candmask,
        const float* __restrict__ b1,
        const float* __restrict__ w2,
        const float* __restrict__ b2,
        float* __restrict__ out)
{
    __shared__ unsigned long long s_key[NN];   // 32 KB
    __shared__ float s_h[128];
    __shared__ float s_part[32];
    __shared__ float s_theta;
    __shared__ int s_hist[256];
    __shared__ int s_cnt;
    __shared__ unsigned long long s_prefix;
    __shared__ int s_k;

    const int b = blockIdx.x;
    const int t = threadIdx.x;
    const float* score = out + BATCH * NN;     // raw scores from main

    if (t == 0) { s_cnt = 0; s_prefix = 0ULL; s_k = KCAP; }

    // ---- theta = relu(sum partials + b1) . w2 + b2 ----
    if (t < 128) {
        float a = b1[t];
        #pragma unroll
        for (int c = 0; c < 8; c++) a += g_hp[b][c][t];
        s_h[t] = fmaxf(a, 0.f) * w2[t];
    }
    __syncthreads();
    if (t < 32) {
        float a = s_h[t] + s_h[t + 32] + s_h[t + 64] + s_h[t + 96];
        #pragma unroll
        for (int o = 16; o > 0; o >>= 1) a += __shfl_xor_sync(0xffffffffu, a, o);
        if (t == 0) { s_theta = a + b2[0]; g_theta[b] = a + b2[0]; }
    }
    __syncthreads();
    const float theta = s_theta;

    // ---- p, keys, count(p>0.5) ----
    int cnt = 0;
    #pragma unroll
    for (int j = 0; j < 4; j++) {
        int i = j * 1024 + t;
        float sc = score[(size_t)b * NN + i];
        float p = 1.0f / (1.0f + expf(-(sc - theta)));
        p *= candmask[(size_t)b * NN + i];
        s_key[i] = ((unsigned long long)__float_as_uint(p) << 32)
                 | (unsigned int)(~i);
        cnt += (p > 0.5f) ? 1 : 0;
    }
    #pragma unroll
    for (int o = 16; o > 0; o >>= 1) cnt += __shfl_xor_sync(0xffffffffu, cnt, o);
    if ((t & 31) == 0) atomicAdd(&s_cnt, cnt);
    __syncthreads();

    const bool trim = (s_cnt > KCAP);
    if (trim) {
        for (int round = 0; round < 8; round++) {
            const int shift = 56 - 8 * round;
            if (t < 256) s_hist[t] = 0;
            __syncthreads();
            const unsigned long long prefix = s_prefix;
            const int hshift = shift + 8;
            #pragma unroll
            for (int j = 0; j < 4; j++) {
                unsigned long long key = s_key[j * 1024 + t];
                bool match = (round == 0) ||
                             ((key >> hshift) == (prefix >> hshift));
                if (match) atomicAdd(&s_hist[(int)((key >> shift) & 255ULL)], 1);
            }
            __syncthreads();
            if (t == 0) {
                int k = s_k, cum = 0, bin = 0;
                for (int byte = 255; byte >= 0; byte--) {
                    cum += s_hist[byte];
                    if (cum >= k) { bin = byte; k -= (cum - s_hist[byte]); break; }
                }
                s_k = k;
                s_prefix = prefix | ((unsigned long long)bin << shift);
            }
            __syncthreads();
        }
    }
    const unsigned long long kth = trim ? s_prefix : 0ULL;
    if (t == 0) g_kth[b] = kth;

    // ---- trimmed sum (deterministic tree reduce) ----
    float lsum = 0.f;
    #pragma unroll
    for (int j = 0; j < 4; j++) {
        unsigned long long key = s_key[j * 1024 + t];
        float p = __uint_as_float((unsigned int)(key >> 32));
        if (key >= kth) lsum += p;        // kth==0 -> keep all
        // (trim && key<kth) -> excluded
    }
    #pragma unroll
    for (int o = 16; o > 0; o >>= 1) lsum += __shfl_xor_sync(0xffffffffu, lsum, o);
    if ((t & 31) == 0) s_part[t >> 5] = lsum;
    __syncthreads();
    if (t < 32) {
        float a = s_part[t];
        #pragma unroll
        for (int o = 16; o > 0; o >>= 1) a += __shfl_xor_sync(0xffffffffu, a, o);
        if (t == 0) {
            float* tail = out + 2 * BATCH * NN;
            tail[b]             = theta;
            tail[BATCH + b]     = a;
            tail[2 * BATCH + b] = a * (1.0f / (float)NN);
        }
    }
}

// ---------------------------------------------------------------------------
// Kernel D: write. grid=64, block=256 — one element per thread.
// Recomputes p (identical arithmetic to select), applies trim, writes outputs.
// ---------------------------------------------------------------------------
__global__ void __launch_bounds__(256) write_kernel(
        const float* __restrict__ candmask,
        float* __restrict__ out)
{
    const int idx = blockIdx.x * 256 + threadIdx.x;   // 0..16383
    const int b = idx >> 12;
    const int i = idx & 4095;
    float* out_hard = out;
    float* out_p    = out + BATCH * NN;

    float sc = out_p[idx];                            // raw score
    float p = 1.0f / (1.0f + expf(-(sc - g_theta[b])));
    p *= candmask[idx];
    unsigned long long key = ((unsigned long long)__float_as_uint(p) << 32)
                           | (unsigned int)(~i);
    if (key < g_kth[b]) p = 0.f;
    out_p[idx]    = p;
    out_hard[idx] = (p > 0.5f) ? 1.0f : 0.0f;
}

// ---------------------------------------------------------------------------
extern "C" void kernel_launch(void* const* d_in, const int* in_sizes, int n_in,
                              void* d_out, int out_size)
{
    const float* x           = (const float*)d_in[0];
    const float* adj         = (const float*)d_in[1];
    const float* seed_ctx    = (const float*)d_in[2];
    const float* local_stats = (const float*)d_in[3];
    const float* cmask       = (const float*)d_in[4];
    const float* candmask    = (const float*)d_in[5];
    const float* Wq          = (const float*)d_in[6];
    const float* Wk          = (const float*)d_in[7];
    const float* w1          = (const float*)d_in[8];
    const float* b1          = (const float*)d_in[9];
    const float* w2          = (const float*)d_in[10];
    const float* b2          = (const float*)d_in[11];
    float* out = (float*)d_out;

    setup_kernel<<<BATCH + BATCH * 8, 256>>>(x, cmask, seed_ctx, local_stats,
                                             Wq, Wk, w1);
    main_kernel<<<BATCH * 256, 512>>>(x, adj, cmask, out + BATCH * NN);
    select_kernel<<<BATCH, 1024>>>(candmask, b1, w2, b2, out);
    write_kernel<<<64, 256>>>(candmask, out);
}

// round 5
// speedup vs baseline: 1.2638x; 1.2638x over previous
#include <cuda_runtime.h>
#include <cuda_bf16.h>
#include <math.h>

// Problem constants
#define BATCH 4
#define NN 4096
#define DD 256
#define PP 64
#define ALPHA 0.2f
#define KCAP 255

// Scratch (no cudaMalloc allowed)
__device__ float g_v[BATCH][DD];            // Wk @ q / sqrt(64)
__device__ float g_hp[BATCH][8][128];       // theta MLP partials (pre-bias)

// ---------------------------------------------------------------------------
// Kernel A: setup. grid = BATCH + BATCH*8, block=256.
//  blocks [0,BATCH): per-batch seed -> q -> v  (reads Wq+Wk, 128 KB)
//  blocks [BATCH,..): theta-MLP partial: 64-input slice -> g_hp[b][chunk][128]
// ---------------------------------------------------------------------------
__global__ void __launch_bounds__(256) setup_kernel(
        const float* __restrict__ x,
        const float* __restrict__ cmask,
        const float* __restrict__ seed_ctx,
        const float* __restrict__ local_stats,
        const float* __restrict__ Wq,
        const float* __restrict__ Wk,
        const float* __restrict__ w1)
{
    const int t = threadIdx.x;

    if (blockIdx.x >= BATCH) {
        // ---- theta MLP partial ----
        __shared__ float s_hp[2][128];
        const int m     = blockIdx.x - BATCH;
        const int b     = m >> 3;
        const int chunk = m & 7;            // 64 inputs
        const int h     = t & 127;
        const int half  = t >> 7;           // 0/1, 32 inputs each
        float a = 0.f;
        #pragma unroll 8
        for (int ii = 0; ii < 32; ii++) {
            int g = chunk * 64 + half * 32 + ii;
            float inv = (g < 384) ? seed_ctx[(size_t)b * 384 + g]
                                  : local_stats[(size_t)b * 128 + (g - 384)];
            a += inv * w1[g * 128 + h];     // coalesced across h
        }
        s_hp[half][h] = a;
        __syncthreads();
        if (t < 128) g_hp[b][chunk][t] = s_hp[0][t] + s_hp[1][t];
        return;
    }

    // ---- seed -> q -> v ----
    __shared__ int   s_seed;
    __shared__ __align__(16) float s_x[DD];
    __shared__ __align__(16) float s_q[PP];
    __shared__ __align__(16) float s_qpart[4][PP];

    const int b    = blockIdx.x;
    const int lane = t & 31;

    if (t == 0) s_seed = NN;
    __syncthreads();

    {   // first index with cmask > 0.5
        int lm = NN;
        #pragma unroll
        for (int j = 15; j >= 0; j--) {
            int i = j * 256 + t;
            if (cmask[(size_t)b * NN + i] > 0.5f) lm = i;
        }
        #pragma unroll
        for (int o = 16; o > 0; o >>= 1)
            lm = min(lm, __shfl_xor_sync(0xffffffffu, lm, o));
        if (lane == 0 && lm < NN) atomicMin(&s_seed, lm);
    }
    __syncthreads();
    const int seed = (s_seed < NN) ? s_seed : 0;

    s_x[t] = x[((size_t)b * NN + seed) * DD + t];
    __syncthreads();

    {   // q[p] = sum_d x_seed[d] * Wq[d,p]
        const int p = t & 63;
        const int c = t >> 6;               // 4 chunks of 64 d's
        float acc = 0.f;
        #pragma unroll 8
        for (int dd = 0; dd < 64; dd++) {
            int d = c * 64 + dd;
            acc += s_x[d] * Wq[d * PP + p];
        }
        s_qpart[c][p] = acc;
    }
    __syncthreads();
    if (t < PP) s_q[t] = s_qpart[0][t] + s_qpart[1][t] + s_qpart[2][t] + s_qpart[3][t];
    __syncthreads();

    {   // v[d] = (Wk[d,:] . q) / 8 ; 4 lanes per row, float4
        const int j = t & 3;
        const float4* q4 = (const float4*)(s_q + j * 16);
        float4 qv0 = q4[0], qv1 = q4[1], qv2 = q4[2], qv3 = q4[3];
        #pragma unroll
        for (int pass = 0; pass < 4; pass++) {
            const int d = pass * 64 + (t >> 2);
            const float4* wk4 = (const float4*)(Wk + d * PP + j * 16);
            float4 w0 = wk4[0], w1v = wk4[1], w2v = wk4[2], w3v = wk4[3];
            float a = w0.x*qv0.x + w0.y*qv0.y + w0.z*qv0.z + w0.w*qv0.w
                    + w1v.x*qv1.x + w1v.y*qv1.y + w1v.z*qv1.z + w1v.w*qv1.w
                    + w2v.x*qv2.x + w2v.y*qv2.y + w2v.z*qv2.z + w2v.w*qv2.w
                    + w3v.x*qv3.x + w3v.y*qv3.y + w3v.z*qv3.z + w3v.w*qv3.w;
            a += __shfl_xor_sync(0xffffffffu, a, 1);
            a += __shfl_xor_sync(0xffffffffu, a, 2);
            if (j == 0) g_v[b][d] = a * 0.125f;
        }
    }
}

// ---------------------------------------------------------------------------
// Kernel B: streaming kernel. One warp per adjacency row, 16 rows/block.
// grid = BATCH * 256, block = 512. Writes RAW scores (theta applied later).
// ---------------------------------------------------------------------------
__global__ void __launch_bounds__(512) main_kernel(
        const float* __restrict__ x,
        const float* __restrict__ adj,
        const float* __restrict__ cmask,
        float* __restrict__ out_score)
{
    __shared__ __align__(16) float s_cm[NN];
    __shared__ __align__(16) float s_v[DD];

    const int b   = blockIdx.x >> 8;
    const int blk = blockIdx.x & 255;
    const int tid = threadIdx.x;

    {
        const float4* cm4 = (const float4*)(cmask + (size_t)b * NN);
        float4* s4 = (float4*)s_cm;
        #pragma unroll
        for (int i = tid; i < NN / 4; i += 512) s4[i] = cm4[i];
        if (tid < DD) s_v[tid] = g_v[b][tid];
    }
    __syncthreads();

    const int w    = tid >> 5;
    const int lane = tid & 31;
    const int n    = (blk << 4) + w;

    const float4* a4 = (const float4*)(adj + ((size_t)b * NN + n) * NN);
    const float4* c4 = (const float4*)s_cm;

    float e2c = 0.f, deg = 0.f;
    #pragma unroll 8
    for (int i = lane; i < NN / 4; i += 32) {
        float4 a = a4[i];
        float4 c = c4[i];
        deg += (a.x + a.y) + (a.z + a.w);
        e2c += a.x * c.x + a.y * c.y + a.z * c.z + a.w * c.w;
    }

    float sc = 0.f;
    const float4* x4 = (const float4*)(x + ((size_t)b * NN + n) * DD);
    const float4* v4 = (const float4*)s_v;
    #pragma unroll
    for (int i = lane; i < DD / 4; i += 32) {
        float4 xv = x4[i];
        float4 vv = v4[i];
        sc += xv.x * vv.x + xv.y * vv.y + xv.z * vv.z + xv.w * vv.w;
    }

    #pragma unroll
    for (int o = 16; o > 0; o >>= 1) {
        e2c += __shfl_xor_sync(0xffffffffu, e2c, o);
        deg += __shfl_xor_sync(0xffffffffu, deg, o);
        sc  += __shfl_xor_sync(0xffffffffu, sc,  o);
    }

    if (lane == 0) {
        deg = fmaxf(deg, 1.0f);
        out_score[(size_t)b * NN + n] = sc + ALPHA * (e2c / deg);
    }
}

// ---------------------------------------------------------------------------
// Kernel C: per-batch finalize. grid=BATCH, block=1024.
// theta reduce -> p/keys -> count -> radix select (parallel suffix-scan bin
// pick, exact jax top-k tie semantics) -> trimmed sums -> write hard/p/tail.
// Output layout: [hard(16384) | p(16384) | theta(4) | expected(4) | mean(4)]
// ---------------------------------------------------------------------------
__global__ void __launch_bounds__(1024) finalize_kernel(
        const float* __restrict__ candmask,
        const float* __restrict__ b1,
        const float* __restrict__ w2,
        const float* __restrict__ b2,
        float* __restrict__ out)
{
    __shared__ unsigned long long s_key[NN];   // 32 KB
    __shared__ float s_h[128];
    __shared__ float s_part[32];
    __shared__ float s_theta;
    __shared__ int s_hist[256];
    __shared__ int s_wsum[8];
    __shared__ int s_cnt;
    __shared__ unsigned long long s_prefix;
    __shared__ int s_k;

    const int b = blockIdx.x;
    const int t = threadIdx.x;
    float* out_hard = out;
    float* out_p    = out + BATCH * NN;        // holds raw scores on entry

    if (t == 0) { s_cnt = 0; s_prefix = 0ULL; s_k = KCAP; }

    // ---- theta = relu(sum partials + b1) . w2 + b2 ----
    if (t < 128) {
        float a = b1[t];
        #pragma unroll
        for (int c = 0; c < 8; c++) a += g_hp[b][c][t];
        s_h[t] = fmaxf(a, 0.f) * w2[t];
    }
    __syncthreads();
    if (t < 32) {
        float a = s_h[t] + s_h[t + 32] + s_h[t + 64] + s_h[t + 96];
        #pragma unroll
        for (int o = 16; o > 0; o >>= 1) a += __shfl_xor_sync(0xffffffffu, a, o);
        if (t == 0) s_theta = a + b2[0];
    }
    __syncthreads();
    const float theta = s_theta;

    // ---- p, keys, count(p>0.5) ----
    int cnt = 0;
    #pragma unroll
    for (int j = 0; j < 4; j++) {
        int i = j * 1024 + t;
        float sc = out_p[(size_t)b * NN + i];
        float p = 1.0f / (1.0f + expf(-(sc - theta)));
        p *= candmask[(size_t)b * NN + i];
        s_key[i] = ((unsigned long long)__float_as_uint(p) << 32)
                 | (unsigned int)(~i);
        cnt += (p > 0.5f) ? 1 : 0;
    }
    #pragma unroll
    for (int o = 16; o > 0; o >>= 1) cnt += __shfl_xor_sync(0xffffffffu, cnt, o);
    if ((t & 31) == 0) atomicAdd(&s_cnt, cnt);
    __syncthreads();

    const bool trim = (s_cnt > KCAP);
    if (trim) {
        for (int round = 0; round < 8; round++) {
            const int shift = 56 - 8 * round;
            // phase 1: snapshot state, clear hist
            const int kreg = s_k;
            const unsigned long long prefix = s_prefix;
            if (t < 256) s_hist[t] = 0;
            __syncthreads();
            // phase 2: histogram of matching keys
            const int hshift = shift + 8;
            #pragma unroll
            for (int j = 0; j < 4; j++) {
                unsigned long long key = s_key[j * 1024 + t];
                bool match = (round == 0) ||
                             ((key >> hshift) == (prefix >> hshift));
                if (match) atomicAdd(&s_hist[(int)((key >> shift) & 255ULL)], 1);
            }
            __syncthreads();
            // phase 3: parallel suffix-scan over 256 bins, pick winner bin
            int h = 0, Sloc = 0;
            if (t < 256) {
                h = s_hist[t];
                Sloc = h;                      // suffix sum within warp
                const int l = t & 31;
                #pragma unroll
                for (int o = 1; o < 32; o <<= 1) {
                    int v = __shfl_down_sync(0xffffffffu, Sloc, o);
                    if (l + o < 32) Sloc += v;
                }
                if (l == 0) s_wsum[t >> 5] = Sloc;
            }
            __syncthreads();
            if (t < 256) {
                int S = Sloc;
                for (int w2i = (t >> 5) + 1; w2i < 8; w2i++) S += s_wsum[w2i];
                // winner: largest byte with S >= k  <=>  S>=k && S-h<k
                if (S >= kreg && (S - h) < kreg) {
                    s_k = kreg - (S - h);
                    s_prefix = prefix | ((unsigned long long)t << shift);
                }
            }
            __syncthreads();
        }
    }
    const unsigned long long kth = trim ? s_prefix : 0ULL;

    // ---- write outputs + trimmed sum (deterministic tree reduce) ----
    float lsum = 0.f;
    #pragma unroll
    for (int j = 0; j < 4; j++) {
        int i = j * 1024 + t;
        unsigned long long key = s_key[i];
        float p = __uint_as_float((unsigned int)(key >> 32));
        if (key < kth) p = 0.f;               // kth==0 -> keep all
        out_p[(size_t)b * NN + i]    = p;
        out_hard[(size_t)b * NN + i] = (p > 0.5f) ? 1.0f : 0.0f;
        lsum += p;
    }
    #pragma unroll
    for (int o = 16; o > 0; o >>= 1) lsum += __shfl_xor_sync(0xffffffffu, lsum, o);
    if ((t & 31) == 0) s_part[t >> 5] = lsum;
    __syncthreads();
    if (t < 32) {
        float a = s_part[t];
        #pragma unroll
        for (int o = 16; o > 0; o >>= 1) a += __shfl_xor_sync(0xffffffffu, a, o);
        if (t == 0) {
            float* tail = out + 2 * BATCH * NN;
            tail[b]             = theta;
            tail[BATCH + b]     = a;
            tail[2 * BATCH + b] = a * (1.0f / (float)NN);
        }
    }
}

// ---------------------------------------------------------------------------
extern "C" void kernel_launch(void* const* d_in, const int* in_sizes, int n_in,
                              void* d_out, int out_size)
{
    const float* x           = (const float*)d_in[0];
    const float* adj         = (const float*)d_in[1];
    const float* seed_ctx    = (const float*)d_in[2];
    const float* local_stats = (const float*)d_in[3];
    const float* cmask       = (const float*)d_in[4];
    const float* candmask    = (const float*)d_in[5];
    const float* Wq          = (const float*)d_in[6];
    const float* Wk          = (const float*)d_in[7];
    const float* w1          = (const float*)d_in[8];
    const float* b1          = (const float*)d_in[9];
    const float* w2          = (const float*)d_in[10];
    const float* b2          = (const float*)d_in[11];
    float* out = (float*)d_out;

    setup_kernel<<<BATCH + BATCH * 8, 256>>>(x, cmask, seed_ctx, local_stats,
                                             Wq, Wk, w1);
    main_kernel<<<BATCH * 256, 512>>>(x, adj, cmask, out + BATCH * NN);
    finalize_kernel<<<BATCH, 1024>>>(candmask, b1, w2, b2, out);
}

// round 8
// speedup vs baseline: 1.3318x; 1.0538x over previous
#include <cuda_runtime.h>
#include <cuda_bf16.h>
#include <math.h>

// Problem constants
#define BATCH 4
#define NN 4096
#define DD 256
#define PP 64
#define ALPHA 0.2f
#define KCAP 255

// Scratch (no cudaMalloc allowed)
__device__ float g_v[BATCH][DD];            // Wk @ q / sqrt(64)
__device__ float g_hp[BATCH][8][128];       // theta MLP partials (pre-bias)

// ---------------------------------------------------------------------------
// Kernel A: setup. grid = BATCH, block = 1024. Only seed -> q -> v.
// Every phase is one wide latency hop (high MLP), minimal serial chain.
// ---------------------------------------------------------------------------
__global__ void __launch_bounds__(1024) setup_kernel(
        const float* __restrict__ x,
        const float* __restrict__ cmask,
        const float* __restrict__ Wq,
        const float* __restrict__ Wk)
{
    __shared__ int   s_seed;
    __shared__ __align__(16) float s_x[DD];
    __shared__ __align__(16) float s_q[PP];
    __shared__ __align__(16) float s_qpart[16][PP];

    const int b    = blockIdx.x;
    const int t    = threadIdx.x;
    const int lane = t & 31;

    if (t == 0) s_seed = NN;
    __syncthreads();

    {   // first index with cmask > 0.5 (4 loads/thread, descending keep-min)
        int lm = NN;
        #pragma unroll
        for (int j = 3; j >= 0; j--) {
            int i = j * 1024 + t;
            if (cmask[(size_t)b * NN + i] > 0.5f) lm = i;
        }
        #pragma unroll
        for (int o = 16; o > 0; o >>= 1)
            lm = min(lm, __shfl_xor_sync(0xffffffffu, lm, o));
        if (lane == 0 && lm < NN) atomicMin(&s_seed, lm);
    }
    __syncthreads();
    const int seed = (s_seed < NN) ? s_seed : 0;

    if (t < DD) s_x[t] = x[((size_t)b * NN + seed) * DD + t];
    __syncthreads();

    {   // q[p] = sum_d x_seed[d] * Wq[d,p] : 16 chunks x 64 p, 16 loads each
        const int p = t & 63;
        const int c = t >> 6;
        float acc = 0.f;
        #pragma unroll
        for (int dd = 0; dd < 16; dd++) {
            int d = c * 16 + dd;
            acc += s_x[d] * Wq[d * PP + p];     // coalesced across p
        }
        s_qpart[c][p] = acc;
    }
    __syncthreads();
    if (t < PP) {
        float a = 0.f;
        #pragma unroll
        for (int c = 0; c < 16; c++) a += s_qpart[c][t];
        s_q[t] = a;
    }
    __syncthreads();

    {   // v[d] = (Wk[d,:] . q) / 8 : 4 lanes per row, 4x float4 each
        const int d = t >> 2;
        const int j = t & 3;
        const float4* wk4 = (const float4*)(Wk + d * PP + j * 16);
        const float4* q4  = (const float4*)(s_q + j * 16);
        float a = 0.f;
        #pragma unroll
        for (int k = 0; k < 4; k++) {
            float4 wv = wk4[k];
            float4 qv = q4[k];
            a += wv.x * qv.x + wv.y * qv.y + wv.z * qv.z + wv.w * qv.w;
        }
        a += __shfl_xor_sync(0xffffffffu, a, 1);
        a += __shfl_xor_sync(0xffffffffu, a, 2);
        if (j == 0) g_v[b][d] = a * 0.125f;
    }
}

// ---------------------------------------------------------------------------
// Kernel B: streaming kernel + theta-MLP tail blocks.
// Blocks [0, BATCH*256): one warp per adj row, 16 rows/block, raw scores.
// Blocks [BATCH*256, +BATCH*8): theta-MLP partial (w1 read hides under the
// DRAM-bound adj stream).
// ---------------------------------------------------------------------------
__global__ void __launch_bounds__(512) main_kernel(
        const float* __restrict__ x,
        const float* __restrict__ adj,
        const float* __restrict__ cmask,
        const float* __restrict__ seed_ctx,
        const float* __restrict__ local_stats,
        const float* __restrict__ w1,
        float* __restrict__ out_score)
{
    if (blockIdx.x >= BATCH * 256) {
        // ---- theta MLP partial: 64-input slice -> g_hp[b][chunk][128] ----
        __shared__ float s_hp[4][128];
        const int m       = blockIdx.x - BATCH * 256;
        const int b       = m >> 3;
        const int chunk   = m & 7;
        const int t       = threadIdx.x;
        const int h       = t & 127;
        const int quarter = t >> 7;            // 0..3, 16 inputs each
        float a = 0.f;
        #pragma unroll
        for (int ii = 0; ii < 16; ii++) {
            int g = chunk * 64 + quarter * 16 + ii;
            float inv = (g < 384) ? seed_ctx[(size_t)b * 384 + g]
                                  : local_stats[(size_t)b * 128 + (g - 384)];
            a += inv * w1[g * 128 + h];        // coalesced across h
        }
        s_hp[quarter][h] = a;
        __syncthreads();
        if (t < 128)
            g_hp[b][chunk][t] = (s_hp[0][t] + s_hp[1][t]) + (s_hp[2][t] + s_hp[3][t]);
        return;
    }

    __shared__ __align__(16) float s_cm[NN];
    __shared__ __align__(16) float s_v[DD];

    const int b   = blockIdx.x >> 8;
    const int blk = blockIdx.x & 255;
    const int tid = threadIdx.x;

    {
        const float4* cm4 = (const float4*)(cmask + (size_t)b * NN);
        float4* s4 = (float4*)s_cm;
        #pragma unroll
        for (int i = tid; i < NN / 4; i += 512) s4[i] = cm4[i];
        if (tid < DD) s_v[tid] = g_v[b][tid];
    }
    __syncthreads();

    const int w    = tid >> 5;
    const int lane = tid & 31;
    const int n    = (blk << 4) + w;

    const float4* a4 = (const float4*)(adj + ((size_t)b * NN + n) * NN);
    const float4* c4 = (const float4*)s_cm;

    float e2c = 0.f, deg = 0.f;
    #pragma unroll 8
    for (int i = lane; i < NN / 4; i += 32) {
        float4 a = a4[i];
        float4 c = c4[i];
        deg += (a.x + a.y) + (a.z + a.w);
        e2c += a.x * c.x + a.y * c.y + a.z * c.z + a.w * c.w;
    }

    float sc = 0.f;
    const float4* x4 = (const float4*)(x + ((size_t)b * NN + n) * DD);
    const float4* v4 = (const float4*)s_v;
    #pragma unroll
    for (int i = lane; i < DD / 4; i += 32) {
        float4 xv = x4[i];
        float4 vv = v4[i];
        sc += xv.x * vv.x + xv.y * vv.y + xv.z * vv.z + xv.w * vv.w;
    }

    #pragma unroll
    for (int o = 16; o > 0; o >>= 1) {
        e2c += __shfl_xor_sync(0xffffffffu, e2c, o);
        deg += __shfl_xor_sync(0xffffffffu, deg, o);
        sc  += __shfl_xor_sync(0xffffffffu, sc,  o);
    }

    if (lane == 0) {
        deg = fmaxf(deg, 1.0f);
        out_score[(size_t)b * NN + n] = sc + ALPHA * (e2c / deg);
    }
}

// ---------------------------------------------------------------------------
// Kernel C: per-batch finalize. grid=BATCH, block=1024.
// theta reduce -> p/keys -> count -> radix select (parallel suffix-scan bin
// pick, exact jax top-k tie semantics) -> write hard/p/tail + trimmed sums.
// Output layout: [hard(16384) | p(16384) | theta(4) | expected(4) | mean(4)]
// ---------------------------------------------------------------------------
__global__ void __launch_bounds__(1024) finalize_kernel(
        const float* __restrict__ candmask,
        const float* __restrict__ b1,
        const float* __restrict__ w2,
        const float* __restrict__ b2,
        float* __restrict__ out)
{
    __shared__ unsigned long long s_key[NN];   // 32 KB
    __shared__ float s_h[128];
    __shared__ float s_part[32];
    __shared__ float s_theta;
    __shared__ int s_hist[256];
    __shared__ int s_wsum[8];
    __shared__ int s_cnt;
    __shared__ unsigned long long s_prefix;
    __shared__ int s_k;

    const int b = blockIdx.x;
    const int t = threadIdx.x;
    float* out_hard = out;
    float* out_p    = out + BATCH * NN;        // holds raw scores on entry

    if (t == 0) { s_cnt = 0; s_prefix = 0ULL; s_k = KCAP; }

    // ---- theta = relu(sum partials + b1) . w2 + b2 ----
    if (t < 128) {
        float a = b1[t];
        #pragma unroll
        for (int c = 0; c < 8; c++) a += g_hp[b][c][t];
        s_h[t] = fmaxf(a, 0.f) * w2[t];
    }
    __syncthreads();
    if (t < 32) {
        float a = s_h[t] + s_h[t + 32] + s_h[t + 64] + s_h[t + 96];
        #pragma unroll
        for (int o = 16; o > 0; o >>= 1) a += __shfl_xor_sync(0xffffffffu, a, o);
        if (t == 0) s_theta = a + b2[0];
    }
    __syncthreads();
    const float theta = s_theta;

    // ---- p, keys, count(p>0.5) ----
    int cnt = 0;
    #pragma unroll
    for (int j = 0; j < 4; j++) {
        int i = j * 1024 + t;
        float sc = out_p[(size_t)b * NN + i];
        float p = 1.0f / (1.0f + expf(-(sc - theta)));
        p *= candmask[(size_t)b * NN + i];
        s_key[i] = ((unsigned long long)__float_as_uint(p) << 32)
                 | (unsigned int)(~i);
        cnt += (p > 0.5f) ? 1 : 0;
    }
    #pragma unroll
    for (int o = 16; o > 0; o >>= 1) cnt += __shfl_xor_sync(0xffffffffu, cnt, o);
    if ((t & 31) == 0) atomicAdd(&s_cnt, cnt);
    __syncthreads();

    const bool trim = (s_cnt > KCAP);
    if (trim) {
        for (int round = 0; round < 8; round++) {
            const int shift = 56 - 8 * round;
            const int kreg = s_k;
            const unsigned long long prefix = s_prefix;
            if (t < 256) s_hist[t] = 0;
            __syncthreads();
            const int hshift = shift + 8;
            #pragma unroll
            for (int j = 0; j < 4; j++) {
                unsigned long long key = s_key[j * 1024 + t];
                bool match = (round == 0) ||
                             ((key >> hshift) == (prefix >> hshift));
                if (match) atomicAdd(&s_hist[(int)((key >> shift) & 255ULL)], 1);
            }
            __syncthreads();
            // parallel suffix-scan over 256 bins, pick winner bin
            int h = 0, Sloc = 0;
            if (t < 256) {
                h = s_hist[t];
                Sloc = h;
                const int l = t & 31;
                #pragma unroll
                for (int o = 1; o < 32; o <<= 1) {
                    int v = __shfl_down_sync(0xffffffffu, Sloc, o);
                    if (l + o < 32) Sloc += v;
                }
                if (l == 0) s_wsum[t >> 5] = Sloc;
            }
            __syncthreads();
            if (t < 256) {
                int S = Sloc;
                for (int w2i = (t >> 5) + 1; w2i < 8; w2i++) S += s_wsum[w2i];
                if (S >= kreg && (S - h) < kreg) {   // unique winner bin
                    s_k = kreg - (S - h);
                    s_prefix = prefix | ((unsigned long long)t << shift);
                }
            }
            __syncthreads();
        }
    }
    const unsigned long long kth = trim ? s_prefix : 0ULL;

    // ---- write outputs + trimmed sum (deterministic tree reduce) ----
    float lsum = 0.f;
    #pragma unroll
    for (int j = 0; j < 4; j++) {
        int i = j * 1024 + t;
        unsigned long long key = s_key[i];
        float p = __uint_as_float((unsigned int)(key >> 32));
        if (key < kth) p = 0.f;               // kth==0 -> keep all
        out_p[(size_t)b * NN + i]    = p;
        out_hard[(size_t)b * NN + i] = (p > 0.5f) ? 1.0f : 0.0f;
        lsum += p;
    }
    #pragma unroll
    for (int o = 16; o > 0; o >>= 1) lsum += __shfl_xor_sync(0xffffffffu, lsum, o);
    if ((t & 31) == 0) s_part[t >> 5] = lsum;
    __syncthreads();
    if (t < 32) {
        float a = s_part[t];
        #pragma unroll
        for (int o = 16; o > 0; o >>= 1) a += __shfl_xor_sync(0xffffffffu, a, o);
        if (t == 0) {
            float* tail = out + 2 * BATCH * NN;
            tail[b]             = theta;
            tail[BATCH + b]     = a;
            tail[2 * BATCH + b] = a * (1.0f / (float)NN);
        }
    }
}

// ---------------------------------------------------------------------------
extern "C" void kernel_launch(void* const* d_in, const int* in_sizes, int n_in,
                              void* d_out, int out_size)
{
    const float* x           = (const float*)d_in[0];
    const float* adj         = (const float*)d_in[1];
    const float* seed_ctx    = (const float*)d_in[2];
    const float* local_stats = (const float*)d_in[3];
    const float* cmask       = (const float*)d_in[4];
    const float* candmask    = (const float*)d_in[5];
    const float* Wq          = (const float*)d_in[6];
    const float* Wk          = (const float*)d_in[7];
    const float* w1          = (const float*)d_in[8];
    const float* b1          = (const float*)d_in[9];
    const float* w2          = (const float*)d_in[10];
    const float* b2          = (const float*)d_in[11];
    float* out = (float*)d_out;

    setup_kernel<<<BATCH, 1024>>>(x, cmask, Wq, Wk);
    main_kernel<<<BATCH * 256 + BATCH * 8, 512>>>(x, adj, cmask, seed_ctx,
                                                  local_stats, w1,
                                                  out + BATCH * NN);
    finalize_kernel<<<BATCH, 1024>>>(candmask, b1, w2, b2, out);
}